// round 11
// baseline (speedup 1.0000x reference)
#include <cuda_runtime.h>

// CGMMTransition: N=10000, L=5, A=6, C=20, C2=20
// Two consecutive n per CTA (grid N/2): one prologue fetch covers both rows of
// stats, halving per-n prologue cost while keeping R6's staggered block-churn
// scheduling (persistent variants regressed in R7/R8).
// Outputs (concatenated in d_out, fp32):
//   p_Q_given_obs        [N, C]           at offset 0
//   transition_posterior [N, L, A, C, C2] at offset N*C
//   rightmost_term       [N, L, A, C, C2] at offset N*C + N*L*A*C*C2

#define LVAL   5
#define AVAL   6
#define CVAL   20
#define C2VAL  20
#define LA     30      // L*A
#define KDIM   600     // LA*C2
#define PER_N  12000   // LA*C*C2
#define PER_N4 3000    // PER_N/4
#define NTHREADS 256
#define NWARPS 8
#define NITER  12      // ceil(3000/256); iter 11 partial (tid < 184)
#define TAIL   (PER_N4 - 11 * NTHREADS)   // 184

__global__ void __launch_bounds__(NTHREADS, 8)
cgmm_kernel(const float* __restrict__ stats,
            const float* __restrict__ layerS,
            const float* __restrict__ arcS,
            const float* __restrict__ T,
            float* __restrict__ out_pq,
            float* __restrict__ out_tp,
            float* __restrict__ out_rt,
            int N)
{
    __shared__ float s_stats[2 * KDIM];        // rows for n0 and n1
    __shared__ float s_inv[2 * LA];
    __shared__ float s_w[LA];
    __shared__ float s_pqw[NWARPS][2][CVAL];   // per-warp, per-n c-bins

    const int tid  = threadIdx.x;
    const int warp = tid >> 5;
    const int lane = tid & 31;

    const int n0 = blockIdx.x * 2;
    const bool has_n1 = (n0 + 1) < N;
    const int nrows = has_n1 ? (2 * LA) : LA;          // valid (l,a) rows
    const int nf4   = has_n1 ? (2 * KDIM / 4) : (KDIM / 4);  // 300 or 150

    // ---- Phase 0: stage stats for BOTH n (300 float4 > 256 thr: stride!) ----
    const float4* g_stats4 =
        reinterpret_cast<const float4*>(stats + (size_t)n0 * KDIM);
    for (int q = tid; q < nf4; q += NTHREADS) {
        float4 v = __ldcs(&g_stats4[q]);     // streamed: each element read once
        reinterpret_cast<float4*>(s_stats)[q] = v;
    }
    // zero ALL 320 bin entries (320 > 256 threads: stride)
    for (int q = tid; q < NWARPS * 2 * CVAL; q += NTHREADS)
        reinterpret_cast<float*>(s_pqw)[q] = 0.0f;
    if (tid < LA) s_w[tid] = layerS[tid / AVAL] * arcS[tid];
    __syncthreads();

    // ---- Phase 1: inverse row-sums for both n (nrows <= 60 < 256) ----
    if (tid < nrows) {
        float s = 0.0f;
        #pragma unroll
        for (int j = 0; j < C2VAL; ++j) s += s_stats[tid * C2VAL + j];
        s_inv[tid] = (s == 0.0f) ? 1.0f : 1.0f / s;
    }
    __syncthreads();

    // ---- Phase 2: two back-to-back streams (R6 body each) ----
    const float4* T4 = reinterpret_cast<const float4*>(T);
    const size_t base0 = (size_t)n0 * PER_N;   // n1 outputs contiguous after n0
    float4* rt4 = reinterpret_cast<float4*>(out_rt + base0);
    float4* tp4 = reinterpret_cast<float4*>(out_tp + base0);

    #pragma unroll
    for (int sel = 0; sel < 2; ++sel) {
        if (sel == 1 && !has_n1) break;
        const int soff = sel * LA;             // row offset into s_stats/s_inv
        const int ioff = sel * PER_N4;         // float4 offset into outputs

        // division-free index state for i = tid + 256*k (element e = 4*i)
        int m    = tid % 5;                    // c2 block = 4*m
        int c    = (tid / 5) % CVAL;
        int la   = tid / 100;
        int r100 = tid % 100;

        #pragma unroll
        for (int k = 0; k < NITER; ++k) {
            const int  i   = tid + k * NTHREADS;
            const bool act = (k < NITER - 1) || (tid < TAIL);

            float v = 0.0f;
            if (act) {
                const float4 t  = __ldg(&T4[i]);   // L1-resident, coalesced
                const float4 sv = *reinterpret_cast<const float4*>(
                                      s_stats + (soff + la) * C2VAL + 4 * m);
                const float inv = s_inv[soff + la];
                const float w   = s_w[la];
                float4 r, p;
                r.x = t.x * sv.x * inv;  r.y = t.y * sv.y * inv;
                r.z = t.z * sv.z * inv;  r.w = t.w * sv.w * inv;
                p.x = r.x * w;  p.y = r.y * w;  p.z = r.z * w;  p.w = r.w * w;
                __stcs(&rt4[ioff + i], r);   // streaming stores
                __stcs(&tp4[ioff + i], p);
                v = (p.x + p.y) + (p.z + p.w);
            }

            // segmented reduction over runs of 5 equal-c lanes (d = 1,2,4)
            float o;
            o = __shfl_down_sync(0xFFFFFFFFu, v, 1);
            if (m <= 3 && lane < 31) v += o;
            o = __shfl_down_sync(0xFFFFFFFFu, v, 2);
            if (m <= 2 && lane < 30) v += o;
            o = __shfl_down_sync(0xFFFFFFFFu, v, 4);
            if (m == 0 && lane < 28) v += o;

            // head lanes have distinct c within a warp-iter -> plain RMW safe
            if (m == 0 || lane == 0) s_pqw[warp][sel][c] += v;

            const bool wrap = (m == 4);
            m = wrap ? 0 : m + 1;
            c += wrap ? 12 : 11;
            if (c >= CVAL) c -= CVAL;
            la += 2; r100 += 56;
            if (r100 >= 100) { la += 1; r100 -= 100; }
        }
    }

    __syncthreads();

    // ---- Epilogue: p_Q for both n (40 < 256 threads) ----
    if (tid < 2 * CVAL) {
        const int sel = tid / CVAL;
        const int c   = tid % CVAL;
        if (sel == 0 || has_n1) {
            float s = 0.0f;
            #pragma unroll
            for (int w8 = 0; w8 < NWARPS; ++w8) s += s_pqw[w8][sel][c];
            out_pq[(size_t)(n0 + sel) * CVAL + c] = s;
        }
    }
}

extern "C" void kernel_launch(void* const* d_in, const int* in_sizes, int n_in,
                              void* d_out, int out_size)
{
    const float* stats  = (const float*)d_in[0];  // [N, L, A, C2]
    const float* layerS = (const float*)d_in[1];  // [L]
    const float* arcS   = (const float*)d_in[2];  // [L, A]
    const float* T      = (const float*)d_in[3];  // [L, A, C, C2]

    const int N = in_sizes[0] / KDIM;

    float* out    = (float*)d_out;
    float* out_pq = out;
    float* out_tp = out_pq + (size_t)N * CVAL;
    float* out_rt = out_tp + (size_t)N * PER_N;

    const int grid = (N + 1) / 2;
    cgmm_kernel<<<grid, NTHREADS>>>(stats, layerS, arcS, T,
                                    out_pq, out_tp, out_rt, N);
}

// round 12
// speedup vs baseline: 3.4052x; 3.4052x over previous
#include <cuda_runtime.h>

// CGMMTransition: N=10000, L=5, A=6, C=20, C2=20
// Half-n blocks: block bid handles n=bid>>1, la-rows [15h, 15h+15) (h=bid&1).
// Small 6-iter hot body (fits L0 I$), fine-grained drain tail, per-half p_Q
// partials combined via global atomicAdd (out_pq pre-zeroed by a tiny kernel).
// Outputs (concatenated in d_out, fp32):
//   p_Q_given_obs        [N, C]           at offset 0
//   transition_posterior [N, L, A, C, C2] at offset N*C
//   rightmost_term       [N, L, A, C, C2] at offset N*C + N*L*A*C*C2

#define LVAL   5
#define AVAL   6
#define CVAL   20
#define C2VAL  20
#define LA     30      // L*A
#define LAH    15      // LA per half-block
#define KDIM   600     // LA*C2
#define KDIMH  300     // stats floats per half
#define PER_N  12000   // LA*C*C2
#define PER_H4 1500    // float4s per half (PER_N/4/2)
#define NTHREADS 256
#define NWARPS 8
#define NITER  6       // ceil(1500/256); iter 5 partial (tid < 220)
#define TAIL   (PER_H4 - 5 * NTHREADS)    // 220

__global__ void zero_pq_kernel(float* __restrict__ out_pq, int total)
{
    int i = blockIdx.x * blockDim.x + threadIdx.x;
    if (i < total) out_pq[i] = 0.0f;
}

__global__ void __launch_bounds__(NTHREADS, 8)
cgmm_kernel(const float* __restrict__ stats,
            const float* __restrict__ layerS,
            const float* __restrict__ arcS,
            const float* __restrict__ T,
            float* __restrict__ out_pq,
            float* __restrict__ out_tp,
            float* __restrict__ out_rt)
{
    __shared__ float s_stats[KDIMH];          // this half's 15 rows
    __shared__ float s_inv[LAH];
    __shared__ float s_w[LAH];
    __shared__ float s_pqw[NWARPS][CVAL];     // per-warp c-bins (non-atomic)

    const int tid  = threadIdx.x;
    const int warp = tid >> 5;
    const int lane = tid & 31;

    const int n  = blockIdx.x >> 1;
    const int h  = blockIdx.x & 1;
    const int la0 = h * LAH;                   // global la base for this half

    // ---- Phase 0: stage this half's stats (75 float4s; guard < 256 OK) ----
    const float4* g_stats4 = reinterpret_cast<const float4*>(
        stats + (size_t)n * KDIM + la0 * C2VAL);
    if (tid < KDIMH / 4) {
        float4 v = __ldcs(&g_stats4[tid]);    // streamed: read exactly once
        reinterpret_cast<float4*>(s_stats)[tid] = v;
    }
    if (tid < NWARPS * CVAL)                   // 160 < 256 OK
        reinterpret_cast<float*>(s_pqw)[tid] = 0.0f;
    if (tid < LAH)                             // 15 < 256 OK
        s_w[tid] = layerS[(la0 + tid) / AVAL] * arcS[la0 + tid];
    __syncthreads();

    // ---- Phase 1: inverse row-sums (15 rows; guard < 256 OK) ----
    if (tid < LAH) {
        float s = 0.0f;
        #pragma unroll
        for (int j = 0; j < C2VAL; ++j) s += s_stats[tid * C2VAL + j];
        s_inv[tid] = (s == 0.0f) ? 1.0f : 1.0f / s;
    }
    __syncthreads();

    // ---- Phase 2: elementwise stream over this half's 1500 float4s ----
    const size_t base4 = (size_t)n * (PER_N / 4) + h * PER_H4;  // f4 offset
    const float4* T4 = reinterpret_cast<const float4*>(T) + h * PER_H4;
    float4* rt4 = reinterpret_cast<float4*>(out_rt) + base4;
    float4* tp4 = reinterpret_cast<float4*>(out_tp) + base4;

    // division-free index state for local i = tid + 256*k (element e = 4*i):
    //   m  = i % 5            (c2 block = 4*m; 1500 = 0 mod 5 so local == global)
    //   c  = (i/5) % 20       (global c too: 300 = 0 mod 20)
    //   la = i / 100 in [0,15)  (local row; +la0 for global)
    int m    = tid % 5;
    int c    = (tid / 5) % CVAL;
    int la   = tid / 100;
    int r100 = tid % 100;

    #pragma unroll
    for (int k = 0; k < NITER; ++k) {
        const int  i   = tid + k * NTHREADS;
        const bool act = (k < NITER - 1) || (tid < TAIL);

        float v = 0.0f;
        if (act) {
            const float4 t  = __ldg(&T4[i]);   // L1-resident, coalesced
            const float4 sv = *reinterpret_cast<const float4*>(
                                  s_stats + la * C2VAL + 4 * m);
            const float inv = s_inv[la];
            const float w   = s_w[la];
            float4 r, p;
            r.x = t.x * sv.x * inv;  r.y = t.y * sv.y * inv;
            r.z = t.z * sv.z * inv;  r.w = t.w * sv.w * inv;
            p.x = r.x * w;  p.y = r.y * w;  p.z = r.z * w;  p.w = r.w * w;
            __stcs(&rt4[i], r);   // streaming stores: don't pollute L2
            __stcs(&tp4[i], p);
            v = (p.x + p.y) + (p.z + p.w);
        }

        // segmented reduction over runs of 5 equal-c lanes (d = 1,2,4)
        float o;
        o = __shfl_down_sync(0xFFFFFFFFu, v, 1);
        if (m <= 3 && lane < 31) v += o;
        o = __shfl_down_sync(0xFFFFFFFFu, v, 2);
        if (m <= 2 && lane < 30) v += o;
        o = __shfl_down_sync(0xFFFFFFFFu, v, 4);
        if (m == 0 && lane < 28) v += o;

        // head lanes have distinct c within a warp-iter -> plain RMW safe
        if (m == 0 || lane == 0) s_pqw[warp][c] += v;

        const bool wrap = (m == 4);
        m = wrap ? 0 : m + 1;
        c += wrap ? 12 : 11;
        if (c >= CVAL) c -= CVAL;
        la += 2; r100 += 56;
        if (r100 >= 100) { la += 1; r100 -= 100; }
    }

    __syncthreads();

    // ---- Epilogue: this half's p_Q partial -> global accumulate ----
    if (tid < CVAL) {
        float s = 0.0f;
        #pragma unroll
        for (int w8 = 0; w8 < NWARPS; ++w8) s += s_pqw[w8][tid];
        atomicAdd(&out_pq[(size_t)n * CVAL + tid], s);   // 2 adds per (n,c)
    }
}

extern "C" void kernel_launch(void* const* d_in, const int* in_sizes, int n_in,
                              void* d_out, int out_size)
{
    const float* stats  = (const float*)d_in[0];  // [N, L, A, C2]
    const float* layerS = (const float*)d_in[1];  // [L]
    const float* arcS   = (const float*)d_in[2];  // [L, A]
    const float* T      = (const float*)d_in[3];  // [L, A, C, C2]

    const int N = in_sizes[0] / KDIM;

    float* out    = (float*)d_out;
    float* out_pq = out;
    float* out_tp = out_pq + (size_t)N * CVAL;
    float* out_rt = out_tp + (size_t)N * PER_N;

    const int pq_total = N * CVAL;
    zero_pq_kernel<<<(pq_total + NTHREADS - 1) / NTHREADS, NTHREADS>>>(
        out_pq, pq_total);
    cgmm_kernel<<<2 * N, NTHREADS>>>(stats, layerS, arcS, T,
                                     out_pq, out_tp, out_rt);
}

// round 13
// speedup vs baseline: 3.4059x; 1.0002x over previous
#include <cuda_runtime.h>

// CGMMTransition: N=10000, L=5, A=6, C=20, C2=20
// Third-n blocks: block bid handles n=bid/3, la-rows [10t, 10t+10) (t=bid%3).
// 4-iter hot body (~2.9KB, fits L0 I$), 50-float4 prologue, grid 30000.
// p_Q partials combined via global atomicAdd (out_pq pre-zeroed).
// Outputs (concatenated in d_out, fp32):
//   p_Q_given_obs        [N, C]           at offset 0
//   transition_posterior [N, L, A, C, C2] at offset N*C
//   rightmost_term       [N, L, A, C, C2] at offset N*C + N*L*A*C*C2

#define LVAL   5
#define AVAL   6
#define CVAL   20
#define C2VAL  20
#define LA     30      // L*A
#define LAT    10      // LA per third-block
#define KDIM   600     // LA*C2
#define KDIMT  200     // stats floats per third
#define PER_N  12000   // LA*C*C2
#define PER_T4 1000    // float4s per third (PER_N/4/3)
#define NTHREADS 256
#define NWARPS 8
#define NITER  4       // ceil(1000/256); iter 3 partial (tid < 232)
#define TAIL   (PER_T4 - 3 * NTHREADS)    // 232

__global__ void zero_pq_kernel(float* __restrict__ out_pq, int total)
{
    int i = blockIdx.x * blockDim.x + threadIdx.x;
    if (i < total) out_pq[i] = 0.0f;
}

__global__ void __launch_bounds__(NTHREADS, 8)
cgmm_kernel(const float* __restrict__ stats,
            const float* __restrict__ layerS,
            const float* __restrict__ arcS,
            const float* __restrict__ T,
            float* __restrict__ out_pq,
            float* __restrict__ out_tp,
            float* __restrict__ out_rt)
{
    __shared__ float s_stats[KDIMT];          // this third's 10 rows
    __shared__ float s_inv[LAT];
    __shared__ float s_w[LAT];
    __shared__ float s_pqw[NWARPS][CVAL];     // per-warp c-bins (non-atomic)

    const int tid  = threadIdx.x;
    const int warp = tid >> 5;
    const int lane = tid & 31;

    const int n   = blockIdx.x / 3;
    const int t3  = blockIdx.x - 3 * n;        // third index 0..2
    const int la0 = t3 * LAT;                  // global la base for this third

    // ---- Phase 0: stage this third's stats (50 float4s; guard < 256 OK) ----
    const float4* g_stats4 = reinterpret_cast<const float4*>(
        stats + (size_t)n * KDIM + la0 * C2VAL);   // byte off 800*t3: aligned
    if (tid < KDIMT / 4) {
        float4 v = __ldcs(&g_stats4[tid]);    // streamed: read exactly once
        reinterpret_cast<float4*>(s_stats)[tid] = v;
    }
    if (tid < NWARPS * CVAL)                   // 160 < 256 OK
        reinterpret_cast<float*>(s_pqw)[tid] = 0.0f;
    if (tid < LAT)                             // 10 < 256 OK
        s_w[tid] = layerS[(la0 + tid) / AVAL] * arcS[la0 + tid];
    __syncthreads();

    // ---- Phase 1: inverse row-sums (10 rows; guard < 256 OK) ----
    if (tid < LAT) {
        float s = 0.0f;
        #pragma unroll
        for (int j = 0; j < C2VAL; ++j) s += s_stats[tid * C2VAL + j];
        s_inv[tid] = (s == 0.0f) ? 1.0f : 1.0f / s;
    }
    __syncthreads();

    // ---- Phase 2: elementwise stream over this third's 1000 float4s ----
    const size_t base4 = (size_t)n * (PER_N / 4) + t3 * PER_T4;  // f4 offset
    const float4* T4 = reinterpret_cast<const float4*>(T) + t3 * PER_T4;
    float4* rt4 = reinterpret_cast<float4*>(out_rt) + base4;
    float4* tp4 = reinterpret_cast<float4*>(out_tp) + base4;

    // division-free index state for local i = tid + 256*k (element e = 4*i):
    //   m  = i % 5        (c2 block = 4*m; 1000 = 0 mod 5 -> local == global)
    //   c  = (i/5) % 20   (global c too: 200 = 0 mod 20)
    //   la = i / 100 in [0,10)  (local row; +la0 for global)
    int m    = tid % 5;
    int c    = (tid / 5) % CVAL;
    int la   = tid / 100;
    int r100 = tid % 100;

    #pragma unroll
    for (int k = 0; k < NITER; ++k) {
        const int  i   = tid + k * NTHREADS;
        const bool act = (k < NITER - 1) || (tid < TAIL);

        float v = 0.0f;
        if (act) {
            const float4 t  = __ldg(&T4[i]);   // L1-resident, coalesced
            const float4 sv = *reinterpret_cast<const float4*>(
                                  s_stats + la * C2VAL + 4 * m);
            const float inv = s_inv[la];
            const float w   = s_w[la];
            float4 r, p;
            r.x = t.x * sv.x * inv;  r.y = t.y * sv.y * inv;
            r.z = t.z * sv.z * inv;  r.w = t.w * sv.w * inv;
            p.x = r.x * w;  p.y = r.y * w;  p.z = r.z * w;  p.w = r.w * w;
            __stcs(&rt4[i], r);   // streaming stores: don't pollute L2
            __stcs(&tp4[i], p);
            v = (p.x + p.y) + (p.z + p.w);
        }

        // segmented reduction over runs of 5 equal-c lanes (d = 1,2,4)
        float o;
        o = __shfl_down_sync(0xFFFFFFFFu, v, 1);
        if (m <= 3 && lane < 31) v += o;
        o = __shfl_down_sync(0xFFFFFFFFu, v, 2);
        if (m <= 2 && lane < 30) v += o;
        o = __shfl_down_sync(0xFFFFFFFFu, v, 4);
        if (m == 0 && lane < 28) v += o;

        // head lanes have distinct c within a warp-iter -> plain RMW safe
        if (m == 0 || lane == 0) s_pqw[warp][c] += v;

        const bool wrap = (m == 4);
        m = wrap ? 0 : m + 1;
        c += wrap ? 12 : 11;
        if (c >= CVAL) c -= CVAL;
        la += 2; r100 += 56;
        if (r100 >= 100) { la += 1; r100 -= 100; }
    }

    __syncthreads();

    // ---- Epilogue: this third's p_Q partial -> global accumulate ----
    if (tid < CVAL) {
        float s = 0.0f;
        #pragma unroll
        for (int w8 = 0; w8 < NWARPS; ++w8) s += s_pqw[w8][tid];
        atomicAdd(&out_pq[(size_t)n * CVAL + tid], s);   // 3 adds per (n,c)
    }
}

extern "C" void kernel_launch(void* const* d_in, const int* in_sizes, int n_in,
                              void* d_out, int out_size)
{
    const float* stats  = (const float*)d_in[0];  // [N, L, A, C2]
    const float* layerS = (const float*)d_in[1];  // [L]
    const float* arcS   = (const float*)d_in[2];  // [L, A]
    const float* T      = (const float*)d_in[3];  // [L, A, C, C2]

    const int N = in_sizes[0] / KDIM;

    float* out    = (float*)d_out;
    float* out_pq = out;
    float* out_tp = out_pq + (size_t)N * CVAL;
    float* out_rt = out_tp + (size_t)N * PER_N;

    const int pq_total = N * CVAL;
    zero_pq_kernel<<<(pq_total + NTHREADS - 1) / NTHREADS, NTHREADS>>>(
        out_pq, pq_total);
    cgmm_kernel<<<3 * N, NTHREADS>>>(stats, layerS, arcS, T,
                                     out_pq, out_tp, out_rt);
}